// round 11
// baseline (speedup 1.0000x reference)
#include <cuda_runtime.h>
#include <cuda_fp16.h>
#include <math.h>

#define BB 8
#define SS 512
#define HH 256
#define AA 64
#define ROWS (BB*SS)   // 4096
#define TI 8           // i-rows per attn block
#define NPROJ 64       // proj blocks (8 per batch), bids 0..63
#define NATTN 512      // attn blocks (64 per batch), bids 64..575

// Scratch (allocation-free rule: __device__ globals)
__device__ float        g_ta[ROWS * AA];         // [row][a], bias folded in (f32)
__device__ unsigned int g_jaT16[(AA/2) * ROWS];  // [a-pair][row], half2
__device__ int          g_flag[BB];              // proj completion counters

namespace rk {

union F2 { unsigned long long u; float2 f; };

__device__ __forceinline__ unsigned long long fma2(
    unsigned long long a, unsigned long long b, unsigned long long c) {
    unsigned long long d;
    asm("fma.rn.f32x2 %0, %1, %2, %3;" : "=l"(d) : "l"(a), "l"(b), "l"(c));
    return d;
}

__device__ __forceinline__ __half2 rk_tanh_f16x2(__half2 x) {
    unsigned int xi = *reinterpret_cast<unsigned int*>(&x);
    unsigned int yi;
    asm("tanh.approx.f16x2 %0, %1;" : "=r"(yi) : "r"(xi));
    return *reinterpret_cast<__half2*>(&yi);
}

// mixed-precision FMA: f16 x f16 + f32 -> f32 (fma pipe, no XU)
__device__ __forceinline__ float fmah(unsigned short a, unsigned short b, float c) {
    float d;
    asm("fma.rn.f32.f16 %0, %1, %2, %3;" : "=f"(d) : "h"(a), "h"(b), "f"(c));
    return d;
}

__device__ __forceinline__ int ld_vol(const int* p) {
    return *reinterpret_cast<const volatile int*>(p);
}

} // namespace rk

using rk::F2;
using rk::fma2;
using rk::rk_tanh_f16x2;
using rk::fmah;
using rk::ld_vol;

// ---------------------------------------------------------------------------
// Kernel 0: reset flags (graph replays reuse device state).
// ---------------------------------------------------------------------------
__global__ void zero_flags_kernel() {
    if (threadIdx.x < BB) g_flag[threadIdx.x] = 0;
}

// ---------------------------------------------------------------------------
// Fused kernel: 576 blocks x 512 threads, 4 blocks/SM -> ONE wave (<=592).
//   bid 0..63    : proj  (batch = bid>>3, rowtile = bid&7 -> 64 rows x 128 cols)
//   bid 64..575  : attn  (idx = bid-64, batch = idx>>6, i0 = (idx&63)*TI)
// launch_bounds(512,4) => <=32 regs; proj may spill slightly (minor phase).
// ---------------------------------------------------------------------------
__global__ void __launch_bounds__(512, 4) fused_kernel(
    const float* __restrict__ x,
    const float* __restrict__ w_ta,
    const float* __restrict__ w_ja,
    const float* __restrict__ bias,
    const float* __restrict__ v,
    float* __restrict__ out)
{
    const int bid = blockIdx.x;
    const int tid = threadIdx.x;

    __shared__ float Xs[64][64];        // proj: [r][kk] 16KB
    __shared__ float Ws[64][128];       // proj: [kk][a2] 32KB
    __shared__ __half2 ta16[AA][4];     // attn: [a][i-pair]
    __shared__ unsigned int v16p[AA/2];
    __shared__ float redm[TI][16];
    __shared__ float reds[TI][16];
    __shared__ float gmaxs[TI];
    __shared__ float sums[TI];

    if (bid < NPROJ) {
        // ============================ PROJ ============================
        const int b       = bid >> 3;
        const int rowtile = bid & 7;
        const int row0    = b * SS + rowtile * 64;

        const int rt = tid >> 5;        // 0..15 (row tile)
        const int ct = tid & 31;        // 0..31 (col tile)

        const int a2w = tid & 127;
        const int hiw = tid >> 7;       // 0..3
        const float* wsrc = (a2w < 64) ? (w_ta + (size_t)a2w * HH)
                                       : (w_ja + (size_t)(a2w - 64) * HH);

        F2 acc[4][2];
#pragma unroll
        for (int i = 0; i < 4; ++i) { acc[i][0].u = 0ull; acc[i][1].u = 0ull; }

        for (int kc = 0; kc < HH; kc += 64) {
            // X chunk: 64 rows x 64 k = 1024 float4, 2 per thread
#pragma unroll
            for (int l = tid; l < 1024; l += 512) {
                int r = l >> 4;
                int q = l & 15;
                float4 xv = *reinterpret_cast<const float4*>(
                    x + (size_t)(row0 + r) * HH + kc + q * 4);
                *reinterpret_cast<float4*>(&Xs[r][q * 4]) = xv;
            }
            // W chunk: thread owns a2w's weight row; float4 along k, STS scatter
#pragma unroll
            for (int m = 0; m < 4; ++m) {
                int kk4 = m * 4 + hiw;  // 0..15
                float4 f = *reinterpret_cast<const float4*>(wsrc + kc + kk4 * 4);
                Ws[kk4 * 4 + 0][a2w] = f.x;
                Ws[kk4 * 4 + 1][a2w] = f.y;
                Ws[kk4 * 4 + 2][a2w] = f.z;
                Ws[kk4 * 4 + 3][a2w] = f.w;
            }
            __syncthreads();

#pragma unroll 8
            for (int kk = 0; kk < 64; ++kk) {
                ulonglong2 wv = *reinterpret_cast<ulonglong2*>(&Ws[kk][ct * 4]);
                F2 xd;
                float a0 = Xs[rt * 4 + 0][kk];   // warp-broadcast
                xd.f = make_float2(a0, a0);
                acc[0][0].u = fma2(xd.u, wv.x, acc[0][0].u);
                acc[0][1].u = fma2(xd.u, wv.y, acc[0][1].u);
                float a1 = Xs[rt * 4 + 1][kk];
                xd.f = make_float2(a1, a1);
                acc[1][0].u = fma2(xd.u, wv.x, acc[1][0].u);
                acc[1][1].u = fma2(xd.u, wv.y, acc[1][1].u);
                float a2v = Xs[rt * 4 + 2][kk];
                xd.f = make_float2(a2v, a2v);
                acc[2][0].u = fma2(xd.u, wv.x, acc[2][0].u);
                acc[2][1].u = fma2(xd.u, wv.y, acc[2][1].u);
                float a3 = Xs[rt * 4 + 3][kk];
                xd.f = make_float2(a3, a3);
                acc[3][0].u = fma2(xd.u, wv.x, acc[3][0].u);
                acc[3][1].u = fma2(xd.u, wv.y, acc[3][1].u);
            }
            __syncthreads();
        }

        const int c0 = ct * 4;
        if (c0 < 64) {
            float4 bb = *reinterpret_cast<const float4*>(bias + c0);
#pragma unroll
            for (int i = 0; i < 4; ++i) {
                int row = row0 + rt * 4 + i;
                float4 o;
                o.x = acc[i][0].f.x + bb.x;
                o.y = acc[i][0].f.y + bb.y;
                o.z = acc[i][1].f.x + bb.z;
                o.w = acc[i][1].f.y + bb.w;
                *reinterpret_cast<float4*>(&g_ta[(size_t)row * AA + c0]) = o;
            }
        } else {
            const int ap0 = (c0 - 64) >> 1;
            uint4 s0, s1;
            __half2 h;
            h = __floats2half2_rn(acc[0][0].f.x, acc[0][0].f.y); s0.x = *reinterpret_cast<unsigned int*>(&h);
            h = __floats2half2_rn(acc[1][0].f.x, acc[1][0].f.y); s0.y = *reinterpret_cast<unsigned int*>(&h);
            h = __floats2half2_rn(acc[2][0].f.x, acc[2][0].f.y); s0.z = *reinterpret_cast<unsigned int*>(&h);
            h = __floats2half2_rn(acc[3][0].f.x, acc[3][0].f.y); s0.w = *reinterpret_cast<unsigned int*>(&h);
            h = __floats2half2_rn(acc[0][1].f.x, acc[0][1].f.y); s1.x = *reinterpret_cast<unsigned int*>(&h);
            h = __floats2half2_rn(acc[1][1].f.x, acc[1][1].f.y); s1.y = *reinterpret_cast<unsigned int*>(&h);
            h = __floats2half2_rn(acc[2][1].f.x, acc[2][1].f.y); s1.z = *reinterpret_cast<unsigned int*>(&h);
            h = __floats2half2_rn(acc[3][1].f.x, acc[3][1].f.y); s1.w = *reinterpret_cast<unsigned int*>(&h);
            const int rowb = row0 + rt * 4;
            *reinterpret_cast<uint4*>(&g_jaT16[(size_t)ap0 * ROWS + rowb])       = s0;
            *reinterpret_cast<uint4*>(&g_jaT16[(size_t)(ap0 + 1) * ROWS + rowb]) = s1;
        }

        // release: all stores visible, then count this block done
        __threadfence();
        __syncthreads();
        if (tid == 0) atomicAdd(&g_flag[b], 1);
        return;
    }

    // ============================ ATTN ============================
    const int idx = bid - NPROJ;
    const int b   = idx >> 6;
    const int i0  = (idx & 63) * TI;
    const int j   = tid;
    const int lane = j & 31;
    const int warp = j >> 5;

    // wait for this batch's proj blocks (8 of them)
    if (tid == 0) {
        while (ld_vol(&g_flag[b]) < 8) __nanosleep(200);
    }
    __syncthreads();

    // setup: pack ta into f16x2 i-pairs; pack v
    if (j < 256) {
        int a = j >> 2, p = j & 3;
        float lo = __ldcg(&g_ta[(size_t)(b * SS + i0 + 2 * p)     * AA + a]);
        float hi = __ldcg(&g_ta[(size_t)(b * SS + i0 + 2 * p + 1) * AA + a]);
        ta16[a][p] = __floats2half2_rn(lo, hi);
    } else if (j < 256 + AA / 2) {
        int ap = j - 256;
        __half2 h = __floats2half2_rn(v[2 * ap], v[2 * ap + 1]);
        v16p[ap] = *reinterpret_cast<unsigned int*>(&h);
    }
    __syncthreads();

    float acc[TI];
#pragma unroll
    for (int i = 0; i < TI; ++i) acc[i] = 0.f;

    const unsigned int* jp = g_jaT16 + b * SS + j;
#pragma unroll 4
    for (int ap = 0; ap < AA / 2; ++ap) {
        unsigned int jraw = __ldcg(&jp[(size_t)ap * ROWS]);
        __half2 jv  = *reinterpret_cast<__half2*>(&jraw);
        __half2 jv0 = __low2half2(jv);
        __half2 jv1 = __high2half2(jv);
        unsigned int vp = v16p[ap];
        unsigned short vh0 = (unsigned short)(vp & 0xffffu);
        unsigned short vh1 = (unsigned short)(vp >> 16);
        uint4 ra0 = *reinterpret_cast<const uint4*>(&ta16[2 * ap][0]);
        uint4 ra1 = *reinterpret_cast<const uint4*>(&ta16[2 * ap + 1][0]);
        const unsigned int* pa0 = reinterpret_cast<const unsigned int*>(&ra0);
        const unsigned int* pa1 = reinterpret_cast<const unsigned int*>(&ra1);
#pragma unroll
        for (int p = 0; p < 4; ++p) {
            __half2 t0 = rk_tanh_f16x2(__hadd2(*reinterpret_cast<const __half2*>(&pa0[p]), jv0));
            __half2 t1 = rk_tanh_f16x2(__hadd2(*reinterpret_cast<const __half2*>(&pa1[p]), jv1));
            unsigned int u0 = *reinterpret_cast<unsigned int*>(&t0);
            unsigned int u1 = *reinterpret_cast<unsigned int*>(&t1);
            acc[2 * p]     = fmah((unsigned short)(u0 & 0xffffu), vh0, acc[2 * p]);
            acc[2 * p]     = fmah((unsigned short)(u1 & 0xffffu), vh1, acc[2 * p]);
            acc[2 * p + 1] = fmah((unsigned short)(u0 >> 16),     vh0, acc[2 * p + 1]);
            acc[2 * p + 1] = fmah((unsigned short)(u1 >> 16),     vh1, acc[2 * p + 1]);
        }
    }

    // ---- block max per row ----
#pragma unroll
    for (int i = 0; i < TI; ++i) {
        float mx = acc[i];
#pragma unroll
        for (int o = 16; o; o >>= 1) mx = fmaxf(mx, __shfl_xor_sync(0xffffffffu, mx, o));
        if (lane == 0) redm[i][warp] = mx;
    }
    __syncthreads();
    if (warp < TI) {
        float m = (lane < 16) ? redm[warp][lane] : -INFINITY;
#pragma unroll
        for (int o = 8; o; o >>= 1) m = fmaxf(m, __shfl_xor_sync(0xffffffffu, m, o));
        if (lane == 0) gmaxs[warp] = m;
    }
    __syncthreads();

    // ---- exp + block sum per row ----
    float e[TI];
#pragma unroll
    for (int i = 0; i < TI; ++i) {
        e[i] = __expf(acc[i] - gmaxs[i]);
        float sm = e[i];
#pragma unroll
        for (int o = 16; o; o >>= 1) sm += __shfl_xor_sync(0xffffffffu, sm, o);
        if (lane == 0) reds[i][warp] = sm;
    }
    __syncthreads();
    if (warp < TI) {
        float t = (lane < 16) ? reds[warp][lane] : 0.f;
#pragma unroll
        for (int o = 8; o; o >>= 1) t += __shfl_xor_sync(0xffffffffu, t, o);
        if (lane == 0) sums[warp] = t;
    }
    __syncthreads();

#pragma unroll
    for (int i = 0; i < TI; ++i) {
        float inv = __fdividef(1.f, sums[i]);
        out[(size_t)(b * SS + i0 + i) * SS + j] = e[i] * inv;
    }
}

// ---------------------------------------------------------------------------
extern "C" void kernel_launch(void* const* d_in, const int* in_sizes, int n_in,
                              void* d_out, int out_size)
{
    const float* x    = (const float*)d_in[0];  // relation_hidden (B,S,H)
    const float* wta  = (const float*)d_in[1];  // (A,H)
    const float* wja  = (const float*)d_in[2];  // (A,H)
    const float* bias = (const float*)d_in[3];  // (1,1,1,A)
    const float* v    = (const float*)d_in[4];  // (1,A)

    zero_flags_kernel<<<1, 32>>>();
    fused_kernel<<<NPROJ + NATTN, 512>>>(x, wta, wja, bias, v, (float*)d_out);
}

// round 12
// speedup vs baseline: 1.8676x; 1.8676x over previous
#include <cuda_runtime.h>
#include <cuda_fp16.h>
#include <math.h>

#define BB 8
#define SS 512
#define HH 256
#define AA 64
#define ROWS (BB*SS)   // 4096
#define TI 8           // i-rows per attn block

// Scratch (allocation-free rule: __device__ globals)
__device__ float        g_ta[ROWS * AA];         // [row][a], bias folded in (f32)
__device__ unsigned int g_jaT16[(AA/2) * ROWS];  // [a-pair][row], half2

namespace rk {

union F2 { unsigned long long u; float2 f; };

__device__ __forceinline__ unsigned long long fma2(
    unsigned long long a, unsigned long long b, unsigned long long c) {
    unsigned long long d;
    asm("fma.rn.f32x2 %0, %1, %2, %3;" : "=l"(d) : "l"(a), "l"(b), "l"(c));
    return d;
}

__device__ __forceinline__ __half2 rk_tanh_f16x2(__half2 x) {
    unsigned int xi = *reinterpret_cast<unsigned int*>(&x);
    unsigned int yi;
    asm("tanh.approx.f16x2 %0, %1;" : "=r"(yi) : "r"(xi));
    return *reinterpret_cast<__half2*>(&yi);
}

// mixed-precision FMA: f16 x f16 + f32 -> f32 (fma pipe, no XU)
__device__ __forceinline__ float fmah(unsigned short a, unsigned short b, float c) {
    float d;
    asm("fma.rn.f32.f16 %0, %1, %2, %3;" : "=f"(d) : "h"(a), "h"(b), "f"(c));
    return d;
}

} // namespace rk

using rk::F2;
using rk::fma2;
using rk::rk_tanh_f16x2;
using rk::fmah;

// ---------------------------------------------------------------------------
// Kernel 1: proj GEMM. 128 blocks x 128 threads. Block: 32 rows x 128 cols.
// Micro-tile 8 rows x 4 cols per thread (rt = tid>>5 -> rows rt*8..+7,
// ct = tid&31 -> cols ct*4). Both smem tiles are [kk][*] with the XOR swizzle
// c ^= ((kk>>2)&7)<<2 : vector reads stay 16B-aligned, x reads are single
// broadcast LDS.128 per 4 rows, stores are <=2-way conflicted.
// ---------------------------------------------------------------------------
__global__ void __launch_bounds__(128) proj_gemm_kernel(
    const float* __restrict__ x,
    const float* __restrict__ w_ta,
    const float* __restrict__ w_ja,
    const float* __restrict__ bias)
{
    __shared__ float Xs[64 * 32];     // [kk][r^swz]   8KB
    __shared__ float Ws[64 * 128];    // [kk][a2^swz] 32KB

    const int tid  = threadIdx.x;
    const int rt   = tid >> 5;        // 0..3  -> rows rt*8..rt*8+7
    const int ct   = tid & 31;        // 0..31 -> cols ct*4..ct*4+3
    const int row0 = blockIdx.x * 32;

    F2 acc[8][2];
#pragma unroll
    for (int i = 0; i < 8; ++i) { acc[i][0].u = 0ull; acc[i][1].u = 0ull; }

    for (int kc = 0; kc < HH; kc += 64) {
        // X chunk: 32 rows x 64 k = 512 float4; coalesced LDG, swizzled STS
#pragma unroll
        for (int m = 0; m < 4; ++m) {
            int idx = tid + m * 128;
            int r = idx >> 4, q = idx & 15;
            float4 f = *reinterpret_cast<const float4*>(
                x + (size_t)(row0 + r) * HH + kc + q * 4);
            int c = r ^ ((q & 7) << 2);
            Xs[(q * 4 + 0) * 32 + c] = f.x;
            Xs[(q * 4 + 1) * 32 + c] = f.y;
            Xs[(q * 4 + 2) * 32 + c] = f.z;
            Xs[(q * 4 + 3) * 32 + c] = f.w;
        }
        // W chunk: 128 a2-rows x 64 k = 2048 float4; coalesced LDG (16 lanes
        // per row), swizzled STS scatter
#pragma unroll
        for (int m = 0; m < 16; ++m) {
            int idx = tid + m * 128;
            int cr = idx >> 4, q = idx & 15;
            const float* wsrc = (cr < 64) ? (w_ta + (size_t)cr * HH)
                                          : (w_ja + (size_t)(cr - 64) * HH);
            float4 f = *reinterpret_cast<const float4*>(wsrc + kc + q * 4);
            int c = cr ^ ((q & 7) << 2);
            Ws[(q * 4 + 0) * 128 + c] = f.x;
            Ws[(q * 4 + 1) * 128 + c] = f.y;
            Ws[(q * 4 + 2) * 128 + c] = f.z;
            Ws[(q * 4 + 3) * 128 + c] = f.w;
        }
        __syncthreads();

#pragma unroll 8
        for (int kk = 0; kk < 64; ++kk) {
            const int swz = ((kk >> 2) & 7) << 2;
            float4 xlo = *reinterpret_cast<const float4*>(&Xs[kk * 32 + ((rt * 8) ^ swz)]);
            float4 xhi = *reinterpret_cast<const float4*>(&Xs[kk * 32 + ((rt * 8 + 4) ^ swz)]);
            ulonglong2 wv = *reinterpret_cast<const ulonglong2*>(&Ws[kk * 128 + ((ct * 4) ^ swz)]);
            F2 xd;
            xd.f = make_float2(xlo.x, xlo.x);
            acc[0][0].u = fma2(xd.u, wv.x, acc[0][0].u);
            acc[0][1].u = fma2(xd.u, wv.y, acc[0][1].u);
            xd.f = make_float2(xlo.y, xlo.y);
            acc[1][0].u = fma2(xd.u, wv.x, acc[1][0].u);
            acc[1][1].u = fma2(xd.u, wv.y, acc[1][1].u);
            xd.f = make_float2(xlo.z, xlo.z);
            acc[2][0].u = fma2(xd.u, wv.x, acc[2][0].u);
            acc[2][1].u = fma2(xd.u, wv.y, acc[2][1].u);
            xd.f = make_float2(xlo.w, xlo.w);
            acc[3][0].u = fma2(xd.u, wv.x, acc[3][0].u);
            acc[3][1].u = fma2(xd.u, wv.y, acc[3][1].u);
            xd.f = make_float2(xhi.x, xhi.x);
            acc[4][0].u = fma2(xd.u, wv.x, acc[4][0].u);
            acc[4][1].u = fma2(xd.u, wv.y, acc[4][1].u);
            xd.f = make_float2(xhi.y, xhi.y);
            acc[5][0].u = fma2(xd.u, wv.x, acc[5][0].u);
            acc[5][1].u = fma2(xd.u, wv.y, acc[5][1].u);
            xd.f = make_float2(xhi.z, xhi.z);
            acc[6][0].u = fma2(xd.u, wv.x, acc[6][0].u);
            acc[6][1].u = fma2(xd.u, wv.y, acc[6][1].u);
            xd.f = make_float2(xhi.w, xhi.w);
            acc[7][0].u = fma2(xd.u, wv.x, acc[7][0].u);
            acc[7][1].u = fma2(xd.u, wv.y, acc[7][1].u);
        }
        __syncthreads();
    }

    const int c0 = ct * 4;
    const int rowb = row0 + rt * 8;
    if (c0 < 64) {
        // ta path: add bias, write [row][a] as float4 (f32)
        float4 bb = *reinterpret_cast<const float4*>(bias + c0);
#pragma unroll
        for (int i = 0; i < 8; ++i) {
            int row = rowb + i;
            float4 o;
            o.x = acc[i][0].f.x + bb.x;
            o.y = acc[i][0].f.y + bb.y;
            o.z = acc[i][1].f.x + bb.z;
            o.w = acc[i][1].f.y + bb.w;
            *reinterpret_cast<float4*>(&g_ta[(size_t)row * AA + c0]) = o;
        }
    } else {
        // ja path: f16x2 over a-pairs, [a-pair][row]; 4-row uint4 stores
        const int ap0 = (c0 - 64) >> 1;
        uint4 sA0, sA1, sB0, sB1;
        __half2 h;
        h = __floats2half2_rn(acc[0][0].f.x, acc[0][0].f.y); sA0.x = *reinterpret_cast<unsigned int*>(&h);
        h = __floats2half2_rn(acc[1][0].f.x, acc[1][0].f.y); sA0.y = *reinterpret_cast<unsigned int*>(&h);
        h = __floats2half2_rn(acc[2][0].f.x, acc[2][0].f.y); sA0.z = *reinterpret_cast<unsigned int*>(&h);
        h = __floats2half2_rn(acc[3][0].f.x, acc[3][0].f.y); sA0.w = *reinterpret_cast<unsigned int*>(&h);
        h = __floats2half2_rn(acc[4][0].f.x, acc[4][0].f.y); sA1.x = *reinterpret_cast<unsigned int*>(&h);
        h = __floats2half2_rn(acc[5][0].f.x, acc[5][0].f.y); sA1.y = *reinterpret_cast<unsigned int*>(&h);
        h = __floats2half2_rn(acc[6][0].f.x, acc[6][0].f.y); sA1.z = *reinterpret_cast<unsigned int*>(&h);
        h = __floats2half2_rn(acc[7][0].f.x, acc[7][0].f.y); sA1.w = *reinterpret_cast<unsigned int*>(&h);
        h = __floats2half2_rn(acc[0][1].f.x, acc[0][1].f.y); sB0.x = *reinterpret_cast<unsigned int*>(&h);
        h = __floats2half2_rn(acc[1][1].f.x, acc[1][1].f.y); sB0.y = *reinterpret_cast<unsigned int*>(&h);
        h = __floats2half2_rn(acc[2][1].f.x, acc[2][1].f.y); sB0.z = *reinterpret_cast<unsigned int*>(&h);
        h = __floats2half2_rn(acc[3][1].f.x, acc[3][1].f.y); sB0.w = *reinterpret_cast<unsigned int*>(&h);
        h = __floats2half2_rn(acc[4][1].f.x, acc[4][1].f.y); sB1.x = *reinterpret_cast<unsigned int*>(&h);
        h = __floats2half2_rn(acc[5][1].f.x, acc[5][1].f.y); sB1.y = *reinterpret_cast<unsigned int*>(&h);
        h = __floats2half2_rn(acc[6][1].f.x, acc[6][1].f.y); sB1.z = *reinterpret_cast<unsigned int*>(&h);
        h = __floats2half2_rn(acc[7][1].f.x, acc[7][1].f.y); sB1.w = *reinterpret_cast<unsigned int*>(&h);
        *reinterpret_cast<uint4*>(&g_jaT16[(size_t)ap0 * ROWS + rowb])           = sA0;
        *reinterpret_cast<uint4*>(&g_jaT16[(size_t)ap0 * ROWS + rowb + 4])       = sA1;
        *reinterpret_cast<uint4*>(&g_jaT16[(size_t)(ap0 + 1) * ROWS + rowb])     = sB0;
        *reinterpret_cast<uint4*>(&g_jaT16[(size_t)(ap0 + 1) * ROWS + rowb + 4]) = sB1;
    }
}

// ---------------------------------------------------------------------------
// Kernel 2: scores + softmax (round-8 version, unchanged). f16x2 tanh + mixed
// fma.rn.f32.f16 accumulation. 512 blocks x 512 threads; thread = one j.
// ---------------------------------------------------------------------------
__global__ void __launch_bounds__(512) attn_kernel(
    const float* __restrict__ v,
    float* __restrict__ out)
{
    __shared__ __half2 ta16[AA][4];     // [a][i-pair p], 16B rows -> LDS.128
    __shared__ unsigned int v16p[AA/2]; // packed (v_2p, v_2p+1) halves
    __shared__ float redm[TI][16];
    __shared__ float reds[TI][16];
    __shared__ float gmaxs[TI];
    __shared__ float sums[TI];

    const int blk = blockIdx.x;           // 0..511
    const int b   = blk >> 6;             // batch
    const int i0  = (blk & 63) * TI;      // first i-row
    const int j   = threadIdx.x;          // 0..511
    const int lane = j & 31;
    const int warp = j >> 5;              // 0..15

    if (j < 256) {
        int a = j >> 2, p = j & 3;
        float lo = g_ta[(size_t)(b * SS + i0 + 2 * p)     * AA + a];
        float hi = g_ta[(size_t)(b * SS + i0 + 2 * p + 1) * AA + a];
        ta16[a][p] = __floats2half2_rn(lo, hi);
    } else if (j < 256 + AA / 2) {
        int ap = j - 256;
        __half2 h = __floats2half2_rn(v[2 * ap], v[2 * ap + 1]);
        v16p[ap] = *reinterpret_cast<unsigned int*>(&h);
    }
    __syncthreads();

    float acc[TI];
#pragma unroll
    for (int i = 0; i < TI; ++i) acc[i] = 0.f;

    const unsigned int* jp = g_jaT16 + b * SS + j;
#pragma unroll 4
    for (int ap = 0; ap < AA / 2; ++ap) {
        unsigned int jraw = jp[(size_t)ap * ROWS];
        __half2 jv  = *reinterpret_cast<__half2*>(&jraw);
        __half2 jv0 = __low2half2(jv);
        __half2 jv1 = __high2half2(jv);
        unsigned int vp = v16p[ap];
        unsigned short vh0 = (unsigned short)(vp & 0xffffu);
        unsigned short vh1 = (unsigned short)(vp >> 16);
        uint4 ra0 = *reinterpret_cast<const uint4*>(&ta16[2 * ap][0]);
        uint4 ra1 = *reinterpret_cast<const uint4*>(&ta16[2 * ap + 1][0]);
        const unsigned int* pa0 = reinterpret_cast<const unsigned int*>(&ra0);
        const unsigned int* pa1 = reinterpret_cast<const unsigned int*>(&ra1);
#pragma unroll
        for (int p = 0; p < 4; ++p) {
            __half2 t0 = rk_tanh_f16x2(__hadd2(*reinterpret_cast<const __half2*>(&pa0[p]), jv0));
            __half2 t1 = rk_tanh_f16x2(__hadd2(*reinterpret_cast<const __half2*>(&pa1[p]), jv1));
            unsigned int u0 = *reinterpret_cast<unsigned int*>(&t0);
            unsigned int u1 = *reinterpret_cast<unsigned int*>(&t1);
            acc[2 * p]     = fmah((unsigned short)(u0 & 0xffffu), vh0, acc[2 * p]);
            acc[2 * p]     = fmah((unsigned short)(u1 & 0xffffu), vh1, acc[2 * p]);
            acc[2 * p + 1] = fmah((unsigned short)(u0 >> 16),     vh0, acc[2 * p + 1]);
            acc[2 * p + 1] = fmah((unsigned short)(u1 >> 16),     vh1, acc[2 * p + 1]);
        }
    }

    // ---- block max per row ----
#pragma unroll
    for (int i = 0; i < TI; ++i) {
        float mx = acc[i];
#pragma unroll
        for (int o = 16; o; o >>= 1) mx = fmaxf(mx, __shfl_xor_sync(0xffffffffu, mx, o));
        if (lane == 0) redm[i][warp] = mx;
    }
    __syncthreads();
    if (warp < TI) {
        float m = (lane < 16) ? redm[warp][lane] : -INFINITY;
#pragma unroll
        for (int o = 8; o; o >>= 1) m = fmaxf(m, __shfl_xor_sync(0xffffffffu, m, o));
        if (lane == 0) gmaxs[warp] = m;
    }
    __syncthreads();

    // ---- exp + block sum per row ----
    float e[TI];
#pragma unroll
    for (int i = 0; i < TI; ++i) {
        e[i] = __expf(acc[i] - gmaxs[i]);
        float sm = e[i];
#pragma unroll
        for (int o = 16; o; o >>= 1) sm += __shfl_xor_sync(0xffffffffu, sm, o);
        if (lane == 0) reds[i][warp] = sm;
    }
    __syncthreads();
    if (warp < TI) {
        float t = (lane < 16) ? reds[warp][lane] : 0.f;
#pragma unroll
        for (int o = 8; o; o >>= 1) t += __shfl_xor_sync(0xffffffffu, t, o);
        if (lane == 0) sums[warp] = t;
    }
    __syncthreads();

#pragma unroll
    for (int i = 0; i < TI; ++i) {
        float inv = __fdividef(1.f, sums[i]);
        out[(size_t)(b * SS + i0 + i) * SS + j] = e[i] * inv;
    }
}

// ---------------------------------------------------------------------------
extern "C" void kernel_launch(void* const* d_in, const int* in_sizes, int n_in,
                              void* d_out, int out_size)
{
    const float* x    = (const float*)d_in[0];  // relation_hidden (B,S,H)
    const float* wta  = (const float*)d_in[1];  // (A,H)
    const float* wja  = (const float*)d_in[2];  // (A,H)
    const float* bias = (const float*)d_in[3];  // (1,1,1,A)
    const float* v    = (const float*)d_in[4];  // (1,A)

    proj_gemm_kernel<<<ROWS / 32, 128>>>(x, wta, wja, bias);
    attn_kernel<<<ROWS / TI, 512>>>(v, (float*)d_out);
}